// round 8
// baseline (speedup 1.0000x reference)
#include <cuda_runtime.h>
#include <cuda_bf16.h>
#include <cstdint>

#define E_DIM 128
#define MT 128
#define NTL 256
#define BMAX 1024
#define NTST 256
#define NEG_BIG (-3.0e38f)
#define VPW 50432

// ---- static device scratch (allocation-free) ----
__device__ __align__(16) __nv_bfloat16 g_Whi[(size_t)VPW * E_DIM];
__device__ __align__(16) __nv_bfloat16 g_Wlo[(size_t)VPW * E_DIM];
__device__ __align__(16) __nv_bfloat16 g_Ahi[(size_t)BMAX * E_DIM];
__device__ __align__(16) __nv_bfloat16 g_Alo[(size_t)BMAX * E_DIM];
__device__ float2 g_stats[(size_t)BMAX * NTST];
__device__ float  g_lse[BMAX];

__device__ __forceinline__ uint32_t smem_u32(const void* p){
  uint32_t a; asm("{ .reg .u64 t; cvta.to.shared.u64 t, %1; cvt.u32.u64 %0, t; }" : "=r"(a) : "l"(p));
  return a;
}
__device__ __forceinline__ void split_bf16(float x, __nv_bfloat16& h, __nv_bfloat16& l){
  h = __float2bfloat16(x);
  l = __float2bfloat16(x - __bfloat162float(h));
}
// swizzled byte offset within a [rows x 128] bf16 tile (256B rows, 16B chunks)
__device__ __forceinline__ uint32_t swoff(int r, int c){
  return (uint32_t)r*256u + (uint32_t)((c ^ (r & 7)) << 4);
}
__device__ __forceinline__ void cp16(uint32_t dst, const void* src){
  asm volatile("cp.async.cg.shared.global [%0], [%1], 16;" :: "r"(dst), "l"(src) : "memory");
}
#define CP_COMMIT() asm volatile("cp.async.commit_group;" ::: "memory")
#define CP_WAIT(n)  asm volatile("cp.async.wait_group %0;" :: "n"(n) : "memory")

__device__ __forceinline__ void ldmA(uint32_t* f, uint32_t base, int r0, int c0, int lid){
  const uint32_t a = (lid < 16) ? base + swoff(r0 + lid, c0)
                                : base + swoff(r0 + lid - 16, c0 + 1);
  asm volatile("ldmatrix.sync.aligned.m8n8.x4.shared.b16 {%0,%1,%2,%3}, [%4];"
    : "=r"(f[0]), "=r"(f[1]), "=r"(f[2]), "=r"(f[3]) : "r"(a));
}
__device__ __forceinline__ void ldmB(uint32_t* f, uint32_t base, int n0, int c0, int lid){
  const int g = lid >> 3, lr = lid & 7;
  const uint32_t a = base + swoff(n0 + lr + ((g & 2) ? 8 : 0), c0 + (g & 1));
  asm volatile("ldmatrix.sync.aligned.m8n8.x4.shared.b16 {%0,%1,%2,%3}, [%4];"
    : "=r"(f[0]), "=r"(f[1]), "=r"(f[2]), "=r"(f[3]) : "r"(a));
}
__device__ __forceinline__ void mma_bf16(float* d, const uint32_t* a, const uint32_t* b){
  asm volatile("mma.sync.aligned.m16n8k16.row.col.f32.bf16.bf16.f32 "
    "{%0,%1,%2,%3}, {%4,%5,%6,%7}, {%8,%9}, {%0,%1,%2,%3};"
    : "+f"(d[0]), "+f"(d[1]), "+f"(d[2]), "+f"(d[3])
    : "r"(a[0]), "r"(a[1]), "r"(a[2]), "r"(a[3]), "r"(b[0]), "r"(b[1]));
}
__device__ __forceinline__ void merge(float& m, float& s, float m2, float s2){
  const float nm = fmaxf(m, m2);
  s = s*__expf(m - nm) + s2*__expf(m2 - nm);
  m = nm;
}

// ---------------- K0: fused prep: wsplit blocks + gather blocks ----------------
__global__ void prep_kernel(const float* __restrict__ W, const float* __restrict__ xs,
                            const float* __restrict__ EM, int V, int NWBLK){
  __shared__ float t[32][33];
  __shared__ int   s_cnt;
  __shared__ int   s_v[1024];
  __shared__ float s_w[1024];
  const int tid = threadIdx.x;

  if ((int)blockIdx.x < NWBLK){
    const int v0 = (blockIdx.x >> 2) * 32, e0 = (blockIdx.x & 3) * 32;
    const int tx = tid & 31, ty = tid >> 5;
#pragma unroll
    for (int k = 0; k < 4; k++){
      const int e = e0 + ty*4 + k, v = v0 + tx;
      t[ty*4+k][tx] = (v < V) ? W[(size_t)e*V + v] : 0.f;
    }
    __syncthreads();
#pragma unroll
    for (int k = 0; k < 4; k++){
      const int a = ty*4 + k;
      const float x = t[tx][a];
      __nv_bfloat16 h, l; split_bf16(x, h, l);
      const size_t o = (size_t)(v0 + a)*E_DIM + e0 + tx;
      g_Whi[o] = h; g_Wlo[o] = l;
    }
    return;
  }

  const int b = blockIdx.x - NWBLK;
  if (tid == 0) s_cnt = 0;
  __syncthreads();

  const float* row = xs + (size_t)b * V;
  int a0 = (int)(((16u - ((unsigned)(uintptr_t)row & 15u)) & 15u) >> 2);
  if (a0 > V) a0 = V;
  const int n4 = (V - a0) >> 2;
  const float4* row4 = (const float4*)(row + a0);

  for (int j = tid; j < n4; j += 256){
    float4 x = row4[j];
    const int base = a0 + 4*j;
    if (x.x != 0.f){ int p = atomicAdd(&s_cnt,1); if (p<1024){ s_v[p]=base;   s_w[p]=x.x; } }
    if (x.y != 0.f){ int p = atomicAdd(&s_cnt,1); if (p<1024){ s_v[p]=base+1; s_w[p]=x.y; } }
    if (x.z != 0.f){ int p = atomicAdd(&s_cnt,1); if (p<1024){ s_v[p]=base+2; s_w[p]=x.z; } }
    if (x.w != 0.f){ int p = atomicAdd(&s_cnt,1); if (p<1024){ s_v[p]=base+3; s_w[p]=x.w; } }
  }
  for (int i = tid; i < a0; i += 256){
    float x = row[i];
    if (x != 0.f){ int p = atomicAdd(&s_cnt,1); if (p<1024){ s_v[p]=i; s_w[p]=x; } }
  }
  for (int i = a0 + 4*n4 + tid; i < V; i += 256){
    float x = row[i];
    if (x != 0.f){ int p = atomicAdd(&s_cnt,1); if (p<1024){ s_v[p]=i; s_w[p]=x; } }
  }
  __syncthreads();

  int cnt = s_cnt; if (cnt > 1024) cnt = 1024;
  if (tid < E_DIM){
    float acc = 0.f;
    for (int k = 0; k < cnt; k++)
      acc = fmaf(s_w[k], EM[(size_t)s_v[k]*E_DIM + tid], acc);
    __nv_bfloat16 h, l; split_bf16(acc, h, l);
    g_Ahi[(size_t)b*E_DIM + tid] = h;
    g_Alo[(size_t)b*E_DIM + tid] = l;
  }
}

// ---------------- K1: mma.sync bf16-split GEMM (128x256 tile), smem-staged stores ----------------
#define SM_AHI 0
#define SM_ALO 32768
#define SM_WHI 65536                 // 64KB (256 rows)
#define SM_WLO 131072                // 64KB
#define SM_L   65536                 // logits stage: f32 [128][258], reuses W region post-MMA
#define LSTR   258
#define SM_STM 0                     // stats: reuse A region post-MMA, f32[128][4]
#define SM_STS 2048
#define SMEM_GEMM (SM_L + 128*LSTR*4)   // 197632

__global__ void __launch_bounds__(512, 1)
gemm_mma_kernel(float* __restrict__ out, int V){
  extern __shared__ char smem[];
  const uint32_t sb = smem_u32(smem);
  const int tid = threadIdx.x, wid = tid >> 5, lid = tid & 31;
  const int wm = wid >> 2, wn = wid & 3;      // 4 x 4 warps: m32 x n64 each
  const int ntile = blockIdx.x, mtile = blockIdx.y;
  const int n0 = ntile * NTL, m0 = mtile * MT;

  // 2-stage async tile fill: group0 = K chunks 0..7, group1 = chunks 8..15
#pragma unroll 1
  for (int half = 0; half < 2; half++){
    const int cb = half * 8;
    for (int idx = tid; idx < 1024; idx += 512){
      const int r = idx >> 3, c = cb + (idx & 7);
      const uint32_t off = swoff(r, c);
      cp16(sb + SM_AHI + off, &((const uint4*)g_Ahi)[(size_t)(m0 + r)*16 + c]);
      cp16(sb + SM_ALO + off, &((const uint4*)g_Alo)[(size_t)(m0 + r)*16 + c]);
    }
    for (int idx = tid; idx < 2048; idx += 512){
      const int r = idx >> 3, c = cb + (idx & 7);
      const uint32_t off = swoff(r, c);
      cp16(sb + SM_WHI + off, &((const uint4*)g_Whi)[(size_t)(n0 + r)*16 + c]);
      cp16(sb + SM_WLO + off, &((const uint4*)g_Wlo)[(size_t)(n0 + r)*16 + c]);
    }
    CP_COMMIT();
  }

  float d[2][8][4];
#pragma unroll
  for (int mf = 0; mf < 2; mf++)
#pragma unroll
    for (int nf = 0; nf < 8; nf++)
#pragma unroll
      for (int k = 0; k < 4; k++) d[mf][nf][k] = 0.f;

  const uint32_t aHi = sb + SM_AHI, aLo = sb + SM_ALO;
  const uint32_t wHi = sb + SM_WHI, wLo = sb + SM_WLO;
  const int rA = 32*wm, rB = 64*wn;

  CP_WAIT(1);
  __syncthreads();

#pragma unroll 1
  for (int sh = 0; sh < 2; sh++){
    if (sh == 1){ CP_WAIT(0); __syncthreads(); }
#pragma unroll 2
    for (int si = 0; si < 4; si++){
      const int c0 = 8*sh + 2*si;
      uint32_t ah[2][4], al[2][4];
      ldmA(ah[0], aHi, rA,      c0, lid);
      ldmA(ah[1], aHi, rA + 16, c0, lid);
      ldmA(al[0], aLo, rA,      c0, lid);
      ldmA(al[1], aLo, rA + 16, c0, lid);
#pragma unroll
      for (int h = 0; h < 2; h++){
        uint32_t wh[4][2], wl[4][2], t[4];
        const int nb = rB + 32*h;
        ldmB(t, wHi, nb,      c0, lid); wh[0][0]=t[0]; wh[0][1]=t[1]; wh[1][0]=t[2]; wh[1][1]=t[3];
        ldmB(t, wHi, nb + 16, c0, lid); wh[2][0]=t[0]; wh[2][1]=t[1]; wh[3][0]=t[2]; wh[3][1]=t[3];
        ldmB(t, wLo, nb,      c0, lid); wl[0][0]=t[0]; wl[0][1]=t[1]; wl[1][0]=t[2]; wl[1][1]=t[3];
        ldmB(t, wLo, nb + 16, c0, lid); wl[2][0]=t[0]; wl[2][1]=t[1]; wl[3][0]=t[2]; wl[3][1]=t[3];
#pragma unroll
        for (int mf = 0; mf < 2; mf++)
#pragma unroll
          for (int j = 0; j < 4; j++){
            float* acc = d[mf][4*h + j];
            mma_bf16(acc, ah[mf], wh[j]);   // hi*hi
            mma_bf16(acc, ah[mf], wl[j]);   // hi*lo
            mma_bf16(acc, al[mf], wh[j]);   // lo*hi
          }
      }
    }
  }
  __syncthreads();   // all LDSM done: A/W smem regions now reusable

  // ---- epilogue: frags -> smem logits (stride 258 kills bank conflicts) + stats ----
  float* L   = (float*)(smem + SM_L);
  float* smM = (float*)(smem + SM_STM);
  float* smS = (float*)(smem + SM_STS);
  const int cq = (lid & 3) * 2;
  const int rq = lid >> 2;

#pragma unroll
  for (int mf = 0; mf < 2; mf++){
    const int rl = 32*wm + 16*mf + rq;
    float mx0 = NEG_BIG, mx1 = NEG_BIG;
#pragma unroll
    for (int nf = 0; nf < 8; nf++){
      const int cl = 64*wn + 8*nf + cq;
      *(float2*)&L[rl*LSTR + cl]     = make_float2(d[mf][nf][0], d[mf][nf][1]);
      *(float2*)&L[(rl+8)*LSTR + cl] = make_float2(d[mf][nf][2], d[mf][nf][3]);
      const int g = n0 + cl;
      if (g   >= V){ d[mf][nf][0] = NEG_BIG; d[mf][nf][2] = NEG_BIG; }
      if (g+1 >= V){ d[mf][nf][1] = NEG_BIG; d[mf][nf][3] = NEG_BIG; }
      mx0 = fmaxf(mx0, fmaxf(d[mf][nf][0], d[mf][nf][1]));
      mx1 = fmaxf(mx1, fmaxf(d[mf][nf][2], d[mf][nf][3]));
    }
    float s0 = 0.f, s1 = 0.f;
#pragma unroll
    for (int nf = 0; nf < 8; nf++){
      s0 += __expf(d[mf][nf][0]-mx0) + __expf(d[mf][nf][1]-mx0);
      s1 += __expf(d[mf][nf][2]-mx1) + __expf(d[mf][nf][3]-mx1);
    }
    if (mx0 == NEG_BIG) s0 = 0.f;
    if (mx1 == NEG_BIG) s1 = 0.f;
#pragma unroll
    for (int o = 1; o <= 2; o <<= 1){
      merge(mx0, s0, __shfl_xor_sync(0xFFFFFFFFu, mx0, o), __shfl_xor_sync(0xFFFFFFFFu, s0, o));
      merge(mx1, s1, __shfl_xor_sync(0xFFFFFFFFu, mx1, o), __shfl_xor_sync(0xFFFFFFFFu, s1, o));
    }
    if ((lid & 3) == 0){
      smM[rl*4 + wn] = mx0;        smS[rl*4 + wn] = s0;
      smM[(rl+8)*4 + wn] = mx1;    smS[(rl+8)*4 + wn] = s1;
    }
  }
  __syncthreads();

  if (tid < 128){
    float m = NEG_BIG, s = 0.f;
#pragma unroll
    for (int k = 0; k < 4; k++) merge(m, s, smM[tid*4 + k], smS[tid*4 + k]);
    g_stats[(size_t)(m0 + tid)*NTST + ntile] = make_float2(m, s);
  }

  // ---- coalesced store pass: smem -> out ----
  const int vlim = V - n0;   // valid cols this tile
#pragma unroll 4
  for (int i = tid; i < 128*256; i += 512){
    const int r = i >> 8, c = i & 255;
    if (c < vlim) out[(size_t)(m0 + r)*V + n0 + c] = L[r*LSTR + c];
  }
}

// ---------------- K2: combine stats -> lse (one warp per row) ----------------
__global__ void lse_kernel(int B, int NT){
  const int w = (blockIdx.x * blockDim.x + threadIdx.x) >> 5;
  const int lid = threadIdx.x & 31;
  if (w >= B) return;
  float m = NEG_BIG, s = 0.f;
  for (int q = lid; q < NT; q += 32){
    const float2 t = g_stats[(size_t)w*NTST + q];
    merge(m, s, t.x, t.y);
  }
#pragma unroll
  for (int o = 16; o; o >>= 1)
    merge(m, s, __shfl_xor_sync(0xFFFFFFFFu, m, o), __shfl_xor_sync(0xFFFFFFFFu, s, o));
  if (lid == 0) g_lse[w] = m + logf(s);
}

// ---------------- K3: subtract lse in-place, 4 segments/row for parallelism ----------------
__global__ void sub_kernel(float* __restrict__ out, int V){
  const int row = blockIdx.x;
  const float lse = g_lse[row];
  const int seg = (V + gridDim.y - 1) / gridDim.y;
  const int s0 = blockIdx.y * seg;
  const int s1 = min(V, s0 + seg);
  if (s0 >= s1) return;
  float* p = out + (size_t)row * V;

  int a0 = s0 + (int)(((16u - ((unsigned)(uintptr_t)(p + s0) & 15u)) & 15u) >> 2);
  if (a0 > s1) a0 = s1;
  for (int i = s0 + threadIdx.x; i < a0; i += blockDim.x) p[i] -= lse;
  const int n4 = (s1 - a0) >> 2;
  float4* p4 = (float4*)(p + a0);
  for (int j = threadIdx.x; j < n4; j += blockDim.x){
    float4 x = p4[j];
    x.x -= lse; x.y -= lse; x.z -= lse; x.w -= lse;
    p4[j] = x;
  }
  for (int i = a0 + 4*n4 + threadIdx.x; i < s1; i += blockDim.x) p[i] -= lse;
}

extern "C" void kernel_launch(void* const* d_in, const int* in_sizes, int n_in,
                              void* d_out, int out_size){
  const float* xs = (const float*)d_in[0];
  const float* EM = (const float*)d_in[2];
  const float* W  = (const float*)d_in[3];
  float* out = (float*)d_out;

  const int V  = in_sizes[3] / E_DIM;          // 50257
  const int B  = in_sizes[0] / V;              // 1024
  const int NT = (V + NTL - 1) / NTL;          // 197
  const int NWBLK = (VPW/32) * 4;              // 6304 wsplit blocks

  cudaFuncSetAttribute(gemm_mma_kernel, cudaFuncAttributeMaxDynamicSharedMemorySize, SMEM_GEMM);

  prep_kernel<<<NWBLK + B, 256>>>(W, xs, EM, V, NWBLK);
  gemm_mma_kernel<<<dim3(NT, B/MT), 512, SMEM_GEMM>>>(out, V);
  lse_kernel<<<(B*32 + 255)/256, 256>>>(B, NT);
  sub_kernel<<<dim3(B, 4), 256>>>(out, V);
}

// round 9
// speedup vs baseline: 1.1020x; 1.1020x over previous
#include <cuda_runtime.h>
#include <cuda_bf16.h>
#include <cstdint>

#define E_DIM 128
#define MT 128
#define NTL 256
#define BMAX 1024
#define NTST 256
#define NEG_BIG (-3.0e38f)
#define VPW 50432

// ---- static device scratch (allocation-free) ----
__device__ __align__(16) float g_Wt[(size_t)VPW * E_DIM];   // W^T, tf32-rounded
__device__ __align__(16) float g_A [(size_t)BMAX * E_DIM];  // xsembeds, tf32-rounded
__device__ float2 g_stats[(size_t)BMAX * NTST];
__device__ float  g_lse[BMAX];

__device__ __forceinline__ uint32_t smem_u32(const void* p){
  uint32_t a; asm("{ .reg .u64 t; cvta.to.shared.u64 t, %1; cvt.u32.u64 %0, t; }" : "=r"(a) : "l"(p));
  return a;
}
__device__ __forceinline__ float to_tf32(float x){
  uint32_t r; asm("cvt.rna.tf32.f32 %0, %1;" : "=r"(r) : "f"(x));
  return __uint_as_float(r);
}
// swizzled byte offset within a [rows x 128] f32 tile (512B rows, 16B chunks, c in 0..31)
__device__ __forceinline__ uint32_t swoff32(int r, int c){
  return (uint32_t)r*512u + (uint32_t)((c ^ (r & 7)) << 4);
}
__device__ __forceinline__ void cp16(uint32_t dst, const void* src){
  asm volatile("cp.async.cg.shared.global [%0], [%1], 16;" :: "r"(dst), "l"(src) : "memory");
}
#define CP_COMMIT() asm volatile("cp.async.commit_group;" ::: "memory")
#define CP_WAIT(n)  asm volatile("cp.async.wait_group %0;" :: "n"(n) : "memory")

// ldmatrix.x4 on f32-as-b16: tiles (r0-7,c0),(r8-15,c0),(r0-7,c0+1),(r8-15,c0+1)
// Yields tf32 m16k8 A-frag (a0..a3) or, for an [N][K] tile, two n8 B-frags: {t0,t2},{t1,t3}.
__device__ __forceinline__ void ldm4(uint32_t* f, uint32_t base, int r0, int c0, int lid){
  const uint32_t a = (lid < 16) ? base + swoff32(r0 + lid, c0)
                                : base + swoff32(r0 + lid - 16, c0 + 1);
  asm volatile("ldmatrix.sync.aligned.m8n8.x4.shared.b16 {%0,%1,%2,%3}, [%4];"
    : "=r"(f[0]), "=r"(f[1]), "=r"(f[2]), "=r"(f[3]) : "r"(a));
}
__device__ __forceinline__ void mma_tf32(float* d, const uint32_t* a, const uint32_t* b){
  asm volatile("mma.sync.aligned.m16n8k8.row.col.f32.tf32.tf32.f32 "
    "{%0,%1,%2,%3}, {%4,%5,%6,%7}, {%8,%9}, {%0,%1,%2,%3};"
    : "+f"(d[0]), "+f"(d[1]), "+f"(d[2]), "+f"(d[3])
    : "r"(a[0]), "r"(a[1]), "r"(a[2]), "r"(a[3]), "r"(b[0]), "r"(b[1]));
}
__device__ __forceinline__ void merge(float& m, float& s, float m2, float s2){
  const float nm = fmaxf(m, m2);
  s = s*__expf(m - nm) + s2*__expf(m2 - nm);
  m = nm;
}

// ---------------- K0: fused prep: W transpose->tf32 blocks + gather blocks ----------------
__global__ void prep_kernel(const float* __restrict__ W, const float* __restrict__ xs,
                            const float* __restrict__ EM, int V, int NWBLK){
  __shared__ float t[32][33];
  __shared__ int   s_cnt;
  __shared__ int   s_v[1024];
  __shared__ float s_w[1024];
  const int tid = threadIdx.x;

  if ((int)blockIdx.x < NWBLK){
    const int v0 = (blockIdx.x >> 2) * 32, e0 = (blockIdx.x & 3) * 32;
    const int tx = tid & 31, ty = tid >> 5;
#pragma unroll
    for (int k = 0; k < 4; k++){
      const int e = e0 + ty*4 + k, v = v0 + tx;
      t[ty*4+k][tx] = (v < V) ? W[(size_t)e*V + v] : 0.f;
    }
    __syncthreads();
#pragma unroll
    for (int k = 0; k < 4; k++){
      const int a = ty*4 + k;
      g_Wt[(size_t)(v0 + a)*E_DIM + e0 + tx] = to_tf32(t[tx][a]);
    }
    return;
  }

  const int b = blockIdx.x - NWBLK;
  if (tid == 0) s_cnt = 0;
  __syncthreads();

  const float* row = xs + (size_t)b * V;
  int a0 = (int)(((16u - ((unsigned)(uintptr_t)row & 15u)) & 15u) >> 2);
  if (a0 > V) a0 = V;
  const int n4 = (V - a0) >> 2;
  const float4* row4 = (const float4*)(row + a0);

  for (int j = tid; j < n4; j += 256){
    float4 x = row4[j];
    const int base = a0 + 4*j;
    if (x.x != 0.f){ int p = atomicAdd(&s_cnt,1); if (p<1024){ s_v[p]=base;   s_w[p]=x.x; } }
    if (x.y != 0.f){ int p = atomicAdd(&s_cnt,1); if (p<1024){ s_v[p]=base+1; s_w[p]=x.y; } }
    if (x.z != 0.f){ int p = atomicAdd(&s_cnt,1); if (p<1024){ s_v[p]=base+2; s_w[p]=x.z; } }
    if (x.w != 0.f){ int p = atomicAdd(&s_cnt,1); if (p<1024){ s_v[p]=base+3; s_w[p]=x.w; } }
  }
  for (int i = tid; i < a0; i += 256){
    float x = row[i];
    if (x != 0.f){ int p = atomicAdd(&s_cnt,1); if (p<1024){ s_v[p]=i; s_w[p]=x; } }
  }
  for (int i = a0 + 4*n4 + tid; i < V; i += 256){
    float x = row[i];
    if (x != 0.f){ int p = atomicAdd(&s_cnt,1); if (p<1024){ s_v[p]=i; s_w[p]=x; } }
  }
  __syncthreads();

  int cnt = s_cnt; if (cnt > 1024) cnt = 1024;
  if (tid < E_DIM){
    float acc = 0.f;
    for (int k = 0; k < cnt; k++)
      acc = fmaf(s_w[k], EM[(size_t)s_v[k]*E_DIM + tid], acc);
    g_A[(size_t)b*E_DIM + tid] = to_tf32(acc);
  }
}

// ---------------- K1: tf32 mma.sync GEMM (128x256 tile, single pass) ----------------
#define SM_A   0                      // 64KB: A tile [128][128] f32
#define SM_W   65536                  // 128KB: W tile [256][128] f32
#define SM_L   65536                  // logits staging reuses W region post-MMA
#define LSTR   258
#define SM_STM 0                      // stats reuse A region post-MMA
#define SM_STS 2048
#define SMEM_GEMM (SM_L + 128*LSTR*4) // 197632

__global__ void __launch_bounds__(512, 1)
gemm_mma_kernel(float* __restrict__ out, int V){
  extern __shared__ char smem[];
  const uint32_t sb = smem_u32(smem);
  const int tid = threadIdx.x, wid = tid >> 5, lid = tid & 31;
  const int wm = wid >> 2, wn = wid & 3;      // 4x4 warps: m32 x n64 each
  const int ntile = blockIdx.x, mtile = blockIdx.y;
  const int n0 = ntile * NTL, m0 = mtile * MT;

  // 2-stage async fill by K halves: chunks 0-15 then 16-31 (16B chunks, 32/row)
#pragma unroll 1
  for (int half = 0; half < 2; half++){
    const int cb = half * 16;
    for (int idx = tid; idx < 2048; idx += 512){
      const int r = idx >> 4, c = cb + (idx & 15);
      cp16(sb + SM_A + swoff32(r, c), &((const uint4*)g_A)[(size_t)(m0 + r)*32 + c]);
    }
    for (int idx = tid; idx < 4096; idx += 512){
      const int r = idx >> 4, c = cb + (idx & 15);
      cp16(sb + SM_W + swoff32(r, c), &((const uint4*)g_Wt)[(size_t)(n0 + r)*32 + c]);
    }
    CP_COMMIT();
  }

  float d[2][8][4];
#pragma unroll
  for (int mf = 0; mf < 2; mf++)
#pragma unroll
    for (int nf = 0; nf < 8; nf++)
#pragma unroll
      for (int k = 0; k < 4; k++) d[mf][nf][k] = 0.f;

  const uint32_t aB = sb + SM_A, wB = sb + SM_W;
  const int rA = 32*wm, rB = 64*wn;

  CP_WAIT(1);
  __syncthreads();

  // 16 k8-steps; step s uses chunks 2s, 2s+1
#pragma unroll 1
  for (int sh = 0; sh < 2; sh++){
    if (sh == 1){ CP_WAIT(0); __syncthreads(); }
#pragma unroll 4
    for (int si = 0; si < 8; si++){
      const int c0 = 16*sh + 2*si;
      uint32_t a[2][4], b[8][2];
      ldm4(a[0], aB, rA,      c0, lid);
      ldm4(a[1], aB, rA + 16, c0, lid);
#pragma unroll
      for (int j = 0; j < 4; j++){
        uint32_t t[4];
        ldm4(t, wB, rB + 16*j, c0, lid);
        b[2*j][0]   = t[0]; b[2*j][1]   = t[2];
        b[2*j+1][0] = t[1]; b[2*j+1][1] = t[3];
      }
#pragma unroll
      for (int mf = 0; mf < 2; mf++)
#pragma unroll
        for (int nf = 0; nf < 8; nf++)
          mma_tf32(d[mf][nf], a[mf], b[nf]);
    }
  }
  __syncthreads();   // all LDSM done: smem reusable

  // ---- epilogue: frags -> smem logits (stride 258) + stats ----
  float* L   = (float*)(smem + SM_L);
  float* smM = (float*)(smem + SM_STM);
  float* smS = (float*)(smem + SM_STS);
  const int cq = (lid & 3) * 2;
  const int rq = lid >> 2;

#pragma unroll
  for (int mf = 0; mf < 2; mf++){
    const int rl = 32*wm + 16*mf + rq;
    float mx0 = NEG_BIG, mx1 = NEG_BIG;
#pragma unroll
    for (int nf = 0; nf < 8; nf++){
      const int cl = 64*wn + 8*nf + cq;
      *(float2*)&L[rl*LSTR + cl]     = make_float2(d[mf][nf][0], d[mf][nf][1]);
      *(float2*)&L[(rl+8)*LSTR + cl] = make_float2(d[mf][nf][2], d[mf][nf][3]);
      const int g = n0 + cl;
      if (g   >= V){ d[mf][nf][0] = NEG_BIG; d[mf][nf][2] = NEG_BIG; }
      if (g+1 >= V){ d[mf][nf][1] = NEG_BIG; d[mf][nf][3] = NEG_BIG; }
      mx0 = fmaxf(mx0, fmaxf(d[mf][nf][0], d[mf][nf][1]));
      mx1 = fmaxf(mx1, fmaxf(d[mf][nf][2], d[mf][nf][3]));
    }
    float s0 = 0.f, s1 = 0.f;
#pragma unroll
    for (int nf = 0; nf < 8; nf++){
      s0 += __expf(d[mf][nf][0]-mx0) + __expf(d[mf][nf][1]-mx0);
      s1 += __expf(d[mf][nf][2]-mx1) + __expf(d[mf][nf][3]-mx1);
    }
    if (mx0 == NEG_BIG) s0 = 0.f;
    if (mx1 == NEG_BIG) s1 = 0.f;
#pragma unroll
    for (int o = 1; o <= 2; o <<= 1){
      merge(mx0, s0, __shfl_xor_sync(0xFFFFFFFFu, mx0, o), __shfl_xor_sync(0xFFFFFFFFu, s0, o));
      merge(mx1, s1, __shfl_xor_sync(0xFFFFFFFFu, mx1, o), __shfl_xor_sync(0xFFFFFFFFu, s1, o));
    }
    if ((lid & 3) == 0){
      smM[rl*4 + wn] = mx0;        smS[rl*4 + wn] = s0;
      smM[(rl+8)*4 + wn] = mx1;    smS[(rl+8)*4 + wn] = s1;
    }
  }
  __syncthreads();

  if (tid < 128){
    float m = NEG_BIG, s = 0.f;
#pragma unroll
    for (int k = 0; k < 4; k++) merge(m, s, smM[tid*4 + k], smS[tid*4 + k]);
    g_stats[(size_t)(m0 + tid)*NTST + ntile] = make_float2(m, s);
  }

  // ---- coalesced store pass: smem -> out ----
  const int vlim = V - n0;
#pragma unroll 4
  for (int i = tid; i < 128*256; i += 512){
    const int r = i >> 8, c = i & 255;
    if (c < vlim) out[(size_t)(m0 + r)*V + n0 + c] = L[r*LSTR + c];
  }
}

// ---------------- K2: combine stats -> lse (one warp per row) ----------------
__global__ void lse_kernel(int B, int NT){
  const int w = (blockIdx.x * blockDim.x + threadIdx.x) >> 5;
  const int lid = threadIdx.x & 31;
  if (w >= B) return;
  float m = NEG_BIG, s = 0.f;
  for (int q = lid; q < NT; q += 32){
    const float2 t = g_stats[(size_t)w*NTST + q];
    merge(m, s, t.x, t.y);
  }
#pragma unroll
  for (int o = 16; o; o >>= 1)
    merge(m, s, __shfl_xor_sync(0xFFFFFFFFu, m, o), __shfl_xor_sync(0xFFFFFFFFu, s, o));
  if (lid == 0) g_lse[w] = m + logf(s);
}

// ---------------- K3: subtract lse in-place (streaming hints) ----------------
__global__ void sub_kernel(float* __restrict__ out, int V){
  const int row = blockIdx.x;
  const float lse = g_lse[row];
  const int seg = (V + gridDim.y - 1) / gridDim.y;
  const int s0 = blockIdx.y * seg;
  const int s1 = min(V, s0 + seg);
  if (s0 >= s1) return;
  float* p = out + (size_t)row * V;

  int a0 = s0 + (int)(((16u - ((unsigned)(uintptr_t)(p + s0) & 15u)) & 15u) >> 2);
  if (a0 > s1) a0 = s1;
  for (int i = s0 + threadIdx.x; i < a0; i += blockDim.x) p[i] -= lse;
  const int n4 = (s1 - a0) >> 2;
  float4* p4 = (float4*)(p + a0);
  for (int j = threadIdx.x; j < n4; j += blockDim.x){
    float4 x = __ldcs(p4 + j);
    x.x -= lse; x.y -= lse; x.z -= lse; x.w -= lse;
    __stcs(p4 + j, x);
  }
  for (int i = a0 + 4*n4 + threadIdx.x; i < s1; i += blockDim.x) p[i] -= lse;
}

extern "C" void kernel_launch(void* const* d_in, const int* in_sizes, int n_in,
                              void* d_out, int out_size){
  const float* xs = (const float*)d_in[0];
  const float* EM = (const float*)d_in[2];
  const float* W  = (const float*)d_in[3];
  float* out = (float*)d_out;

  const int V  = in_sizes[3] / E_DIM;          // 50257
  const int B  = in_sizes[0] / V;              // 1024
  const int NT = (V + NTL - 1) / NTL;          // 197
  const int NWBLK = (VPW/32) * 4;              // 6304 wsplit blocks

  cudaFuncSetAttribute(gemm_mma_kernel, cudaFuncAttributeMaxDynamicSharedMemorySize, SMEM_GEMM);

  prep_kernel<<<NWBLK + B, 256>>>(W, xs, EM, V, NWBLK);
  gemm_mma_kernel<<<dim3(NT, B/MT), 512, SMEM_GEMM>>>(out, V);
  lse_kernel<<<(B*32 + 255)/256, 256>>>(B, NT);
  sub_kernel<<<dim3(B, 4), 256>>>(out, V);
}

// round 11
// speedup vs baseline: 1.2573x; 1.1409x over previous
#include <cuda_runtime.h>
#include <cuda_bf16.h>
#include <cstdint>

#define E_DIM 128
#define BMAX 1024
#define NTST 32
#define NCID 19
#define NEG_BIG (-3.0e38f)
#define VPW 50432

// ---- static device scratch (allocation-free) ----
__device__ __align__(16) float g_Wt[(size_t)VPW * E_DIM];   // W^T, tf32-rounded
__device__ __align__(16) float g_A [(size_t)BMAX * E_DIM];  // xsembeds, tf32-rounded
__device__ float2 g_stats[(size_t)BMAX * NTST];
__device__ float  g_lse[BMAX];

__device__ __forceinline__ uint32_t smem_u32(const void* p){
  uint32_t a; asm("{ .reg .u64 t; cvta.to.shared.u64 t, %1; cvt.u32.u64 %0, t; }" : "=r"(a) : "l"(p));
  return a;
}
__device__ __forceinline__ float to_tf32(float x){
  uint32_t r; asm("cvt.rna.tf32.f32 %0, %1;" : "=r"(r) : "f"(x));
  return __uint_as_float(r);
}
// swizzled byte offset within a [rows x 128] f32 tile (512B rows, 16B chunks, c in 0..31)
__device__ __forceinline__ uint32_t swoff32(int r, int c){
  return (uint32_t)r*512u + (uint32_t)((c ^ (r & 7)) << 4);
}
__device__ __forceinline__ void cp16(uint32_t dst, const void* src){
  asm volatile("cp.async.cg.shared.global [%0], [%1], 16;" :: "r"(dst), "l"(src) : "memory");
}
#define CP_COMMIT() asm volatile("cp.async.commit_group;" ::: "memory")
#define CP_WAIT(n)  asm volatile("cp.async.wait_group %0;" :: "n"(n) : "memory")

// ldmatrix.x4 on f32-as-b16 (validated in R9)
__device__ __forceinline__ void ldm4(uint32_t* f, uint32_t base, int r0, int c0, int lid){
  const uint32_t a = (lid < 16) ? base + swoff32(r0 + lid, c0)
                                : base + swoff32(r0 + lid - 16, c0 + 1);
  asm volatile("ldmatrix.sync.aligned.m8n8.x4.shared.b16 {%0,%1,%2,%3}, [%4];"
    : "=r"(f[0]), "=r"(f[1]), "=r"(f[2]), "=r"(f[3]) : "r"(a));
}
__device__ __forceinline__ void mma_tf32(float* d, const uint32_t* a, const uint32_t* b){
  asm volatile("mma.sync.aligned.m16n8k8.row.col.f32.tf32.tf32.f32 "
    "{%0,%1,%2,%3}, {%4,%5,%6,%7}, {%8,%9}, {%0,%1,%2,%3};"
    : "+f"(d[0]), "+f"(d[1]), "+f"(d[2]), "+f"(d[3])
    : "r"(a[0]), "r"(a[1]), "r"(a[2]), "r"(a[3]), "r"(b[0]), "r"(b[1]));
}
__device__ __forceinline__ void merge(float& m, float& s, float m2, float s2){
  const float nm = fmaxf(m, m2);
  s = s*__expf(m - nm) + s2*__expf(m2 - nm);
  m = nm;
}

// ---------------- K0: fused prep (unchanged) ----------------
__global__ void prep_kernel(const float* __restrict__ W, const float* __restrict__ xs,
                            const float* __restrict__ EM, int V, int NWBLK){
  __shared__ float t[32][33];
  __shared__ int   s_cnt;
  __shared__ int   s_v[1024];
  __shared__ float s_w[1024];
  const int tid = threadIdx.x;

  if ((int)blockIdx.x < NWBLK){
    const int v0 = (blockIdx.x >> 2) * 32, e0 = (blockIdx.x & 3) * 32;
    const int tx = tid & 31, ty = tid >> 5;
#pragma unroll
    for (int k = 0; k < 4; k++){
      const int e = e0 + ty*4 + k, v = v0 + tx;
      t[ty*4+k][tx] = (v < V) ? W[(size_t)e*V + v] : 0.f;
    }
    __syncthreads();
#pragma unroll
    for (int k = 0; k < 4; k++){
      const int a = ty*4 + k;
      g_Wt[(size_t)(v0 + a)*E_DIM + e0 + tx] = to_tf32(t[tx][a]);
    }
    return;
  }

  const int b = blockIdx.x - NWBLK;
  if (tid == 0) s_cnt = 0;
  __syncthreads();

  const float* row = xs + (size_t)b * V;
  int a0 = (int)(((16u - ((unsigned)(uintptr_t)row & 15u)) & 15u) >> 2);
  if (a0 > V) a0 = V;
  const int n4 = (V - a0) >> 2;
  const float4* row4 = (const float4*)(row + a0);

  for (int j = tid; j < n4; j += 256){
    float4 x = row4[j];
    const int base = a0 + 4*j;
    if (x.x != 0.f){ int p = atomicAdd(&s_cnt,1); if (p<1024){ s_v[p]=base;   s_w[p]=x.x; } }
    if (x.y != 0.f){ int p = atomicAdd(&s_cnt,1); if (p<1024){ s_v[p]=base+1; s_w[p]=x.y; } }
    if (x.z != 0.f){ int p = atomicAdd(&s_cnt,1); if (p<1024){ s_v[p]=base+2; s_w[p]=x.z; } }
    if (x.w != 0.f){ int p = atomicAdd(&s_cnt,1); if (p<1024){ s_v[p]=base+3; s_w[p]=x.w; } }
  }
  for (int i = tid; i < a0; i += 256){
    float x = row[i];
    if (x != 0.f){ int p = atomicAdd(&s_cnt,1); if (p<1024){ s_v[p]=i; s_w[p]=x; } }
  }
  for (int i = a0 + 4*n4 + tid; i < V; i += 256){
    float x = row[i];
    if (x != 0.f){ int p = atomicAdd(&s_cnt,1); if (p<1024){ s_v[p]=i; s_w[p]=x; } }
  }
  __syncthreads();

  int cnt = s_cnt; if (cnt > 1024) cnt = 1024;
  if (tid < E_DIM){
    float acc = 0.f;
    for (int k = 0; k < cnt; k++)
      acc = fmaf(s_w[k], EM[(size_t)s_v[k]*E_DIM + tid], acc);
    g_A[(size_t)b*E_DIM + tid] = to_tf32(acc);
  }
}

// ---------------- K1: persistent tf32 GEMM: A resident, W double-buffered ----------------
// R10 bug fixed: buffers are now indexed by LOCAL tile parity (i - nt0),
// matching the prologue's unconditional fill of buffer 0.
#define SM_A   0                       // 64KB
#define SM_W0  65536                   // 64KB
#define SM_W1  131072                  // 64KB
#define SM_STM 196608                  // f32[128][4]
#define SM_STS (196608 + 2048)
#define SMEM_GEMM (196608 + 4096)

__global__ void __launch_bounds__(512, 1)
gemm_mma_kernel(float* __restrict__ out, int V, int NTt, int TPC){
  extern __shared__ char smem[];
  const uint32_t sb = smem_u32(smem);
  const int tid = threadIdx.x, wid = tid >> 5, lid = tid & 31;
  const int wm = wid >> 2, wn = wid & 3;   // 4x4 warps: each m32 x n32
  const int cid = blockIdx.x, mtile = blockIdx.y;
  const int m0 = mtile * 128;
  const int nt0 = cid * TPC;
  const int nt1 = min(NTt, nt0 + TPC);
  if (nt0 >= nt1) return;

  // prologue: A fill + W(nt0) fill into LOCAL buf0, one group
  for (int idx = tid; idx < 4096; idx += 512){
    const int r = idx >> 5, c = idx & 31;
    cp16(sb + SM_A + swoff32(r, c), &((const uint4*)g_A)[(size_t)(m0 + r)*32 + c]);
  }
  {
    const int n0 = nt0 * 128;
    for (int idx = tid; idx < 4096; idx += 512){
      const int r = idx >> 5, c = idx & 31;
      cp16(sb + SM_W0 + swoff32(r, c), &((const uint4*)g_Wt)[(size_t)(n0 + r)*32 + c]);
    }
  }
  CP_COMMIT();

  const int rA = 32*wm, rB = 32*wn;
  const int cq = (lid & 3) * 2;
  const int rq = lid >> 2;
  float rm[4], rs[4];
#pragma unroll
  for (int j = 0; j < 4; j++){ rm[j] = NEG_BIG; rs[j] = 0.f; }

  for (int i = nt0; i < nt1; i++){
    const int lb = (i - nt0) & 1;                       // LOCAL parity (fix)
    const uint32_t wB = sb + (lb ? SM_W1 : SM_W0);
    const int n0 = i * 128;

    CP_WAIT(0);
    __syncthreads();                    // W(i) (and A) ready; prior stage reads done

    if (i + 1 < nt1){                   // prefetch W(i+1) into other LOCAL buffer
      const uint32_t wN = sb + (lb ? SM_W0 : SM_W1);
      const int nn = (i + 1) * 128;
      for (int idx = tid; idx < 4096; idx += 512){
        const int r = idx >> 5, c = idx & 31;
        cp16(wN + swoff32(r, c), &((const uint4*)g_Wt)[(size_t)(nn + r)*32 + c]);
      }
      CP_COMMIT();
    }

    // ---- MMA: 16 k8-steps ----
    float d[2][4][4];
#pragma unroll
    for (int mf = 0; mf < 2; mf++)
#pragma unroll
      for (int nf = 0; nf < 4; nf++)
#pragma unroll
        for (int k = 0; k < 4; k++) d[mf][nf][k] = 0.f;

#pragma unroll 4
    for (int s = 0; s < 16; s++){
      const int c0 = 2*s;
      uint32_t a[2][4], b[4][2];
      ldm4(a[0], sb + SM_A, rA,      c0, lid);
      ldm4(a[1], sb + SM_A, rA + 16, c0, lid);
#pragma unroll
      for (int j = 0; j < 2; j++){
        uint32_t t[4];
        ldm4(t, wB, rB + 16*j, c0, lid);
        b[2*j][0]   = t[0]; b[2*j][1]   = t[2];
        b[2*j+1][0] = t[1]; b[2*j+1][1] = t[3];
      }
#pragma unroll
      for (int mf = 0; mf < 2; mf++)
#pragma unroll
        for (int nf = 0; nf < 4; nf++)
          mma_tf32(d[mf][nf], a[mf], b[nf]);
    }
    __syncthreads();                    // LDSM done: wB reusable as logits stage

    // ---- stage logits into wB (swizzled) + update running stats ----
    char* Lb = smem + (lb ? SM_W1 : SM_W0);
#pragma unroll
    for (int mf = 0; mf < 2; mf++){
      const int rl = rA + 16*mf + rq;
      float mx0 = NEG_BIG, mx1 = NEG_BIG;
#pragma unroll
      for (int nf = 0; nf < 4; nf++){
        const int cl = rB + 8*nf + cq;
        const uint32_t o0 = swoff32(rl,   cl >> 2) + (cl & 3)*4;
        const uint32_t o1 = swoff32(rl+8, cl >> 2) + (cl & 3)*4;
        *(float2*)(Lb + o0) = make_float2(d[mf][nf][0], d[mf][nf][1]);
        *(float2*)(Lb + o1) = make_float2(d[mf][nf][2], d[mf][nf][3]);
        const int g = n0 + cl;
        if (g   >= V){ d[mf][nf][0] = NEG_BIG; d[mf][nf][2] = NEG_BIG; }
        if (g+1 >= V){ d[mf][nf][1] = NEG_BIG; d[mf][nf][3] = NEG_BIG; }
        mx0 = fmaxf(mx0, fmaxf(d[mf][nf][0], d[mf][nf][1]));
        mx1 = fmaxf(mx1, fmaxf(d[mf][nf][2], d[mf][nf][3]));
      }
      float s0 = 0.f, s1 = 0.f;
#pragma unroll
      for (int nf = 0; nf < 4; nf++){
        s0 += __expf(d[mf][nf][0]-mx0) + __expf(d[mf][nf][1]-mx0);
        s1 += __expf(d[mf][nf][2]-mx1) + __expf(d[mf][nf][3]-mx1);
      }
      if (mx0 == NEG_BIG) s0 = 0.f;
      if (mx1 == NEG_BIG) s1 = 0.f;
      merge(rm[2*mf],   rs[2*mf],   mx0, s0);
      merge(rm[2*mf+1], rs[2*mf+1], mx1, s1);
    }
    __syncthreads();

    // ---- coalesced store: stage -> out ----
    const int vlim = min(128, V - n0);
#pragma unroll 4
    for (int idx = tid; idx < 128*128; idx += 512){
      const int r = idx >> 7, c = idx & 127;
      if (c < vlim)
        out[(size_t)(m0 + r)*V + n0 + c] =
          *(const float*)(Lb + swoff32(r, c >> 2) + (c & 3)*4);
    }
    __syncthreads();
  }

  // ---- final stats: reduce 4 lanes sharing rows, then 4 wn warps ----
  float* smM = (float*)(smem + SM_STM);
  float* smS = (float*)(smem + SM_STS);
#pragma unroll
  for (int j = 0; j < 4; j++){
#pragma unroll
    for (int o = 1; o <= 2; o <<= 1)
      merge(rm[j], rs[j], __shfl_xor_sync(0xFFFFFFFFu, rm[j], o),
                          __shfl_xor_sync(0xFFFFFFFFu, rs[j], o));
  }
  if ((lid & 3) == 0){
#pragma unroll
    for (int j = 0; j < 4; j++){
      const int rloc = rA + 16*(j >> 1) + 8*(j & 1) + rq;
      smM[rloc*4 + wn] = rm[j];
      smS[rloc*4 + wn] = rs[j];
    }
  }
  __syncthreads();
  if (tid < 128){
    float m = NEG_BIG, s = 0.f;
#pragma unroll
    for (int k = 0; k < 4; k++) merge(m, s, smM[tid*4 + k], smS[tid*4 + k]);
    g_stats[(size_t)(m0 + tid)*NTST + cid] = make_float2(m, s);
  }
}

// ---------------- K2: combine stats -> lse (one warp per row) ----------------
__global__ void lse_kernel(int B, int NQ){
  const int w = (blockIdx.x * blockDim.x + threadIdx.x) >> 5;
  const int lid = threadIdx.x & 31;
  if (w >= B) return;
  float m = NEG_BIG, s = 0.f;
  for (int q = lid; q < NQ; q += 32){
    const float2 t = g_stats[(size_t)w*NTST + q];
    merge(m, s, t.x, t.y);
  }
#pragma unroll
  for (int o = 16; o; o >>= 1)
    merge(m, s, __shfl_xor_sync(0xFFFFFFFFu, m, o), __shfl_xor_sync(0xFFFFFFFFu, s, o));
  if (lid == 0) g_lse[w] = m + logf(s);
}

// ---------------- K3: subtract lse in-place ----------------
__global__ void sub_kernel(float* __restrict__ out, int V){
  const int row = blockIdx.x;
  const float lse = g_lse[row];
  const int seg = (V + gridDim.y - 1) / gridDim.y;
  const int s0 = blockIdx.y * seg;
  const int s1 = min(V, s0 + seg);
  if (s0 >= s1) return;
  float* p = out + (size_t)row * V;

  int a0 = s0 + (int)(((16u - ((unsigned)(uintptr_t)(p + s0) & 15u)) & 15u) >> 2);
  if (a0 > s1) a0 = s1;
  for (int i = s0 + threadIdx.x; i < a0; i += blockDim.x) p[i] -= lse;
  const int n4 = (s1 - a0) >> 2;
  float4* p4 = (float4*)(p + a0);
  for (int j = threadIdx.x; j < n4; j += blockDim.x){
    float4 x = __ldcs(p4 + j);
    x.x -= lse; x.y -= lse; x.z -= lse; x.w -= lse;
    __stcs(p4 + j, x);
  }
  for (int i = a0 + 4*n4 + threadIdx.x; i < s1; i += blockDim.x) p[i] -= lse;
}

extern "C" void kernel_launch(void* const* d_in, const int* in_sizes, int n_in,
                              void* d_out, int out_size){
  const float* xs = (const float*)d_in[0];
  const float* EM = (const float*)d_in[2];
  const float* W  = (const float*)d_in[3];
  float* out = (float*)d_out;

  const int V   = in_sizes[3] / E_DIM;         // 50257
  const int B   = in_sizes[0] / V;             // 1024
  const int NTt = (V + 127) / 128;             // 393
  const int TPC = (NTt + NCID - 1) / NCID;     // 21
  const int NWBLK = (VPW/32) * 4;              // 6304 wsplit blocks

  cudaFuncSetAttribute(gemm_mma_kernel, cudaFuncAttributeMaxDynamicSharedMemorySize, SMEM_GEMM);

  prep_kernel<<<NWBLK + B, 256>>>(W, xs, EM, V, NWBLK);
  gemm_mma_kernel<<<dim3(NCID, B/128), 512, SMEM_GEMM>>>(out, V, NTt, TPC);
  lse_kernel<<<(B*32 + 255)/256, 256>>>(B, NCID);
  sub_kernel<<<dim3(B, 4), 256>>>(out, V);
}